// round 2
// baseline (speedup 1.0000x reference)
#include <cuda_runtime.h>
#include <math.h>

#define B_ 32
#define L_ 720
#define N_ 512
#define H_ 16
#define D_ 64
#define TOPK_ 8
#define M_ (B_*L_)   // 23040

// ---------------- scratch (static device memory; no allocations) ----------------
__device__ float g_Q[N_*H_];
__device__ float g_K[N_*H_];
__device__ int   g_idx[N_*TOPK_];
__device__ float g_w[N_*TOPK_];
__device__ float g_center_raw[B_*N_];
__device__ float g_center[B_*N_];
__device__ float g_cg[B_*N_];           // center @ Wg[N:2N]  (per batch)
__device__ float g_ring[(size_t)M_*N_];
__device__ float g_fused[(size_t)M_*N_];
__device__ float g_h[(size_t)M_*N_];

// ---------------- 1. Q/K projection (tiny) ----------------
__global__ void qk_kernel(const float* __restrict__ ve,
                          const float* __restrict__ Wq, const float* __restrict__ bq,
                          const float* __restrict__ Wk, const float* __restrict__ bk) {
    int n = blockIdx.x * blockDim.x + threadIdx.x;
    if (n >= N_) return;
    float v[H_];
#pragma unroll
    for (int j = 0; j < H_; j++) v[j] = ve[n*H_+j];
#pragma unroll
    for (int h = 0; h < H_; h++) {
        float q = bq[h], k = bk[h];
#pragma unroll
        for (int j = 0; j < H_; j++) {
            q += v[j]*Wq[j*H_+h];
            k += v[j]*Wk[j*H_+h];
        }
        g_Q[n*H_+h] = q;
        g_K[n*H_+h] = k;
    }
}

// ---------------- 2. sim row + top-8 + softmax weights ----------------
__global__ void topk_kernel() {
    int n = blockIdx.x;
    int tid = threadIdx.x;   // 128 threads
    __shared__ float sim[N_];
    __shared__ float q[H_];
    __shared__ float rv[128];
    __shared__ int   ri[128];
    __shared__ float tv[TOPK_];
    __shared__ int   tix[TOPK_];

    if (tid < H_) q[tid] = g_Q[n*H_+tid];
    __syncthreads();

    for (int m = tid; m < N_; m += 128) {
        float s = 0.f;
#pragma unroll
        for (int j = 0; j < H_; j++) s += q[j]*g_K[m*H_+j];
        sim[m] = (m == n) ? -1e9f : s;
    }
    __syncthreads();

    for (int t = 0; t < TOPK_; t++) {
        float bv = -1e30f; int bi = 0x7fffffff;
        for (int m = tid; m < N_; m += 128) {
            float s = sim[m];
            if (s > bv) { bv = s; bi = m; }
        }
        rv[tid] = bv; ri[tid] = bi;
        __syncthreads();
        for (int off = 64; off > 0; off >>= 1) {
            if (tid < off) {
                float ov = rv[tid+off]; int oi = ri[tid+off];
                if (ov > rv[tid] || (ov == rv[tid] && oi < ri[tid])) { rv[tid] = ov; ri[tid] = oi; }
            }
            __syncthreads();
        }
        if (tid == 0) { tv[t] = rv[0]; tix[t] = ri[0]; sim[ri[0]] = -1e30f; }
        __syncthreads();
    }
    if (tid == 0) {
        float mx = tv[0];   // values sorted descending
        float e[TOPK_]; float s = 0.f;
#pragma unroll
        for (int t = 0; t < TOPK_; t++) { e[t] = expf(tv[t]-mx); s += e[t]; }
        float inv = 1.f/s;
#pragma unroll
        for (int t = 0; t < TOPK_; t++) { g_w[n*TOPK_+t] = e[t]*inv; g_idx[n*TOPK_+t] = tix[t]; }
    }
}

// ---------------- 3. center attention (softmax over L, weighted sum) ----------------
__global__ void center_attn_kernel(const float* __restrict__ x,
                                   const float* __restrict__ Wscore,
                                   const float* __restrict__ bscore) {
    int b = blockIdx.x, tid = threadIdx.x;   // 256 threads
    __shared__ float p[L_];
    __shared__ float red[256];
    const float* xb = x + (size_t)b*L_*N_;

    for (int l = tid; l < L_; l += 256) {
        float s = bscore[0];
        const float* xr = xb + (size_t)l*N_;
        for (int nn = 0; nn < N_; nn += 4) {
            float4 v  = *(const float4*)(xr + nn);
            float4 w4 = *(const float4*)(Wscore + nn);
            s += v.x*w4.x + v.y*w4.y + v.z*w4.z + v.w*w4.w;
        }
        p[l] = s;
    }
    __syncthreads();

    float m = -1e30f;
    for (int l = tid; l < L_; l += 256) m = fmaxf(m, p[l]);
    red[tid] = m; __syncthreads();
    for (int off = 128; off > 0; off >>= 1) { if (tid < off) red[tid] = fmaxf(red[tid], red[tid+off]); __syncthreads(); }
    m = red[0];
    __syncthreads();

    float s = 0.f;
    for (int l = tid; l < L_; l += 256) { float e = expf(p[l]-m); p[l] = e; s += e; }
    red[tid] = s; __syncthreads();
    for (int off = 128; off > 0; off >>= 1) { if (tid < off) red[tid] += red[tid+off]; __syncthreads(); }
    float inv = 1.f/red[0];
    __syncthreads();
    for (int l = tid; l < L_; l += 256) p[l] *= inv;
    __syncthreads();

    for (int nn = tid; nn < N_; nn += 256) {
        float acc = 0.f;
        for (int l = 0; l < L_; l++) acc += p[l]*xb[(size_t)l*N_+nn];
        g_center_raw[b*N_+nn] = acc;
    }
}

// ---------------- 4. center MLP + fold center through Wg bottom half ----------------
__global__ void mlp_kernel(const float* __restrict__ Wc1, const float* __restrict__ bc1,
                           const float* __restrict__ Wc2, const float* __restrict__ bc2,
                           const float* __restrict__ Wcn, const float* __restrict__ bcn,
                           const float* __restrict__ Wg) {
    int b = blockIdx.x, tid = threadIdx.x;   // 256 threads
    __shared__ float cr[N_];
    __shared__ float c1[D_];
    __shared__ float c2[D_];
    __shared__ float ctr[N_];
    for (int n = tid; n < N_; n += 256) cr[n] = g_center_raw[b*N_+n];
    __syncthreads();
    if (tid < D_) {
        float s = bc1[tid];
        for (int n = 0; n < N_; n++) s += cr[n]*Wc1[n*D_+tid];
        c1[tid] = 0.5f*s*(1.f + erff(s*0.7071067811865475f));
    }
    __syncthreads();
    if (tid < D_) {
        float s = bc2[tid];
#pragma unroll
        for (int e = 0; e < D_; e++) s += c1[e]*Wc2[e*D_+tid];
        c2[tid] = 0.5f*s*(1.f + erff(s*0.7071067811865475f));
    }
    __syncthreads();
    for (int n = tid; n < N_; n += 256) {
        float s = bcn[n];
#pragma unroll
        for (int d = 0; d < D_; d++) s += c2[d]*Wcn[d*N_+n];
        ctr[n] = s;
        g_center[b*N_+n] = s;
    }
    __syncthreads();
    for (int n2 = tid; n2 < N_; n2 += 256) {
        float s = 0.f;
        for (int n = 0; n < N_; n++) s += ctr[n]*Wg[(size_t)(N_+n)*N_ + n2];
        g_cg[b*N_+n2] = s;
    }
}

// ---------------- 5. ring gather: out[b,l,n] = sum_k x[b,l,idx[n,k]] * w[n,k] ----------------
#define TL 8
__global__ void ring_kernel(const float* __restrict__ x) {
    int b  = blockIdx.y;
    int l0 = blockIdx.x * TL;
    int tid = threadIdx.x;   // 256 threads
    __shared__ float xt[TL][N_];
    const float* xb = x + (size_t)b*L_*N_ + (size_t)l0*N_;
    for (int i = tid; i < TL*N_/4; i += 256)
        ((float4*)xt)[i] = ((const float4*)xb)[i];
    __syncthreads();
    float* outb = g_ring + (size_t)b*L_*N_ + (size_t)l0*N_;
    for (int o = tid; o < TL*N_; o += 256) {
        int l = o >> 9, n = o & 511;
        float acc = 0.f;
#pragma unroll
        for (int k = 0; k < TOPK_; k++) {
            int id  = __ldg(&g_idx[n*TOPK_+k]);
            float w = __ldg(&g_w[n*TOPK_+k]);
            acc += xt[l][id] * w;
        }
        outb[o] = acc;
    }
}

// ---------------- 6/7. fp32 tiled GEMM (M=23040, N=512, K=512) with fused epilogues -------
// mode 0: A=g_ring,  W=Wg_top, e0=bg  -> gate+mix epilogue (uses g_cg, g_center globals) -> g_fused
// mode 1: A=g_fused, W=Wf,     e0=bf, e1=x -> +bias+residual -> g_h
__global__ __launch_bounds__(256) void gemm_kernel(int mode,
                                                   const float* __restrict__ W,
                                                   const float* __restrict__ e0,
                                                   const float* __restrict__ e1) {
    __shared__ float As[16][64];   // transposed: As[k][m]
    __shared__ float Bs[16][64];   // Bs[k][n]
    const float* A = (mode == 0) ? g_ring  : g_fused;
    float*       C = (mode == 0) ? g_fused : g_h;

    int tid  = threadIdx.x;
    int row0 = blockIdx.x * 64;
    int col0 = blockIdx.y * 64;
    int tx = tid & 15, ty = tid >> 4;
    int am = tid >> 2;            // A-tile row 0..63
    int ac = (tid & 3) * 4;       // A-tile k-col {0,4,8,12}
    int bk = tid >> 4;            // B-tile k row 0..15
    int bn = (tid & 15) * 4;      // B-tile col

    float acc[4][4] = {};

    for (int kk = 0; kk < N_; kk += 16) {
        float4 av = *(const float4*)(A + (size_t)(row0+am)*N_ + kk + ac);
        As[ac+0][am] = av.x; As[ac+1][am] = av.y; As[ac+2][am] = av.z; As[ac+3][am] = av.w;
        *(float4*)(&Bs[bk][bn]) = *(const float4*)(W + (size_t)(kk+bk)*N_ + col0 + bn);
        __syncthreads();
#pragma unroll
        for (int k = 0; k < 16; k++) {
            float4 a  = *(float4*)(&As[k][ty*4]);
            float4 bv = *(float4*)(&Bs[k][tx*4]);
            float ar[4] = {a.x, a.y, a.z, a.w};
            float br[4] = {bv.x, bv.y, bv.z, bv.w};
#pragma unroll
            for (int i = 0; i < 4; i++)
#pragma unroll
                for (int j = 0; j < 4; j++)
                    acc[i][j] += ar[i]*br[j];
        }
        __syncthreads();
    }

#pragma unroll
    for (int i = 0; i < 4; i++) {
        int r  = row0 + ty*4 + i;
        int bb = r / L_;
#pragma unroll
        for (int j = 0; j < 4; j++) {
            int c = col0 + tx*4 + j;
            size_t off = (size_t)r*N_ + c;
            float v = acc[i][j];
            if (mode == 0) {
                float pre = v + g_cg[bb*N_+c] + e0[c];
                float g   = 1.f/(1.f + expf(-pre));
                float rv  = A[off];
                C[off] = g*rv + (1.f-g)*g_center[bb*N_+c];
            } else {
                C[off] = v + e0[c] + e1[off];
            }
        }
    }
}

// ---------------- 8. LayerNorm over N ----------------
__global__ void ln_kernel(const float* __restrict__ gamma, const float* __restrict__ beta,
                          float* __restrict__ out) {
    int r = blockIdx.x, tid = threadIdx.x;   // 256 threads, 2 elems each
    const float* hr = g_h + (size_t)r*N_;
    float a  = hr[tid];
    float b2 = hr[tid+256];
    __shared__ float rs[256], rq[256];
    rs[tid] = a + b2;
    rq[tid] = a*a + b2*b2;
    __syncthreads();
    for (int off = 128; off > 0; off >>= 1) {
        if (tid < off) { rs[tid] += rs[tid+off]; rq[tid] += rq[tid+off]; }
        __syncthreads();
    }
    float mu  = rs[0] * (1.f/N_);
    float var = rq[0] * (1.f/N_) - mu*mu;
    float inv = rsqrtf(var + 1e-5f);
    size_t base = (size_t)r*N_;
    out[base+tid]     = (a  - mu)*inv*gamma[tid]     + beta[tid];
    out[base+tid+256] = (b2 - mu)*inv*gamma[tid+256] + beta[tid+256];
}

// ---------------- launch ----------------
extern "C" void kernel_launch(void* const* d_in, const int* in_sizes, int n_in,
                              void* d_out, int out_size) {
    const float* x      = (const float*)d_in[0];
    const float* ve     = (const float*)d_in[1];
    const float* Wq     = (const float*)d_in[2];
    const float* bq     = (const float*)d_in[3];
    const float* Wk     = (const float*)d_in[4];
    const float* bk     = (const float*)d_in[5];
    const float* Wscore = (const float*)d_in[6];
    const float* bscore = (const float*)d_in[7];
    const float* Wc1    = (const float*)d_in[8];
    const float* bc1    = (const float*)d_in[9];
    const float* Wc2    = (const float*)d_in[10];
    const float* bc2    = (const float*)d_in[11];
    const float* Wcn    = (const float*)d_in[12];
    const float* bcn    = (const float*)d_in[13];
    const float* Wg     = (const float*)d_in[14];
    const float* bg     = (const float*)d_in[15];
    const float* Wf     = (const float*)d_in[16];
    const float* bf     = (const float*)d_in[17];
    const float* gamma  = (const float*)d_in[18];
    const float* beta   = (const float*)d_in[19];
    float* out = (float*)d_out;

    qk_kernel<<<2, 256>>>(ve, Wq, bq, Wk, bk);
    topk_kernel<<<512, 128>>>();
    center_attn_kernel<<<B_, 256>>>(x, Wscore, bscore);
    mlp_kernel<<<B_, 256>>>(Wc1, bc1, Wc2, bc2, Wcn, bcn, Wg);
    ring_kernel<<<dim3(L_/TL, B_), 256>>>(x);

    // gate GEMM + sigmoid mix (uses Wg top half: rows 0..511; g_cg/g_center read as device globals)
    gemm_kernel<<<dim3(M_/64, N_/64), 256>>>(0, Wg, bg, nullptr);
    // Wf GEMM + bias + residual
    gemm_kernel<<<dim3(M_/64, N_/64), 256>>>(1, Wf, bf, x);

    ln_kernel<<<M_, 256>>>(gamma, beta, out);
}

// round 6
// speedup vs baseline: 1.6164x; 1.6164x over previous
#include <cuda_runtime.h>
#include <cuda_bf16.h>
#include <mma.h>
#include <math.h>
#include <stdint.h>

using namespace nvcuda;

#define B_ 32
#define L_ 720
#define N_ 512
#define H_ 16
#define D_ 64
#define TOPK_ 8
#define M_ (B_*L_)   // 23040

// ---------------- scratch (static device memory; no allocations) ----------------
__device__ float g_Q[N_*H_];
__device__ float g_K[N_*H_];
__device__ int   g_idx[N_*TOPK_];
__device__ float g_w[N_*TOPK_];
__device__ float g_logit[B_*L_];
__device__ float g_prob[B_*L_];
__device__ float g_center_raw[B_*N_];
__device__ float g_center[B_*N_];
__device__ float g_cg[B_*N_];
__device__ float g_ring[(size_t)M_*N_];
__device__ float g_fused[(size_t)M_*N_];
__device__ float g_h[(size_t)M_*N_];

// ---------------- helpers ----------------
__device__ __forceinline__ void bsplit(float v, __nv_bfloat16& h, __nv_bfloat16& l) {
    h = __float2bfloat16(v);
    l = __float2bfloat16(v - __bfloat162float(h));
}

// ---------------- 1. Q/K projection ----------------
__global__ void qk_kernel(const float* __restrict__ ve,
                          const float* __restrict__ Wq, const float* __restrict__ bq,
                          const float* __restrict__ Wk, const float* __restrict__ bk) {
    int n = blockIdx.x * blockDim.x + threadIdx.x;
    if (n >= N_) return;
    float v[H_];
#pragma unroll
    for (int j = 0; j < H_; j++) v[j] = ve[n*H_+j];
#pragma unroll
    for (int h = 0; h < H_; h++) {
        float q = bq[h], k = bk[h];
#pragma unroll
        for (int j = 0; j < H_; j++) { q += v[j]*Wq[j*H_+h]; k += v[j]*Wk[j*H_+h]; }
        g_Q[n*H_+h] = q; g_K[n*H_+h] = k;
    }
}

// ---------------- 2. top-8 + softmax weights ----------------
__global__ void topk_kernel() {
    int n = blockIdx.x, tid = threadIdx.x;   // 128 threads
    __shared__ float sim[N_];
    __shared__ float q[H_];
    __shared__ float rv[128];
    __shared__ int   ri[128];
    __shared__ float tv[TOPK_];
    __shared__ int   tix[TOPK_];
    if (tid < H_) q[tid] = g_Q[n*H_+tid];
    __syncthreads();
    for (int m = tid; m < N_; m += 128) {
        float s = 0.f;
#pragma unroll
        for (int j = 0; j < H_; j++) s += q[j]*g_K[m*H_+j];
        sim[m] = (m == n) ? -1e9f : s;
    }
    __syncthreads();
    for (int t = 0; t < TOPK_; t++) {
        float bv = -1e30f; int bi = 0x7fffffff;
        for (int m = tid; m < N_; m += 128) {
            float s = sim[m];
            if (s > bv) { bv = s; bi = m; }
        }
        rv[tid] = bv; ri[tid] = bi;
        __syncthreads();
        for (int off = 64; off > 0; off >>= 1) {
            if (tid < off) {
                float ov = rv[tid+off]; int oi = ri[tid+off];
                if (ov > rv[tid] || (ov == rv[tid] && oi < ri[tid])) { rv[tid] = ov; ri[tid] = oi; }
            }
            __syncthreads();
        }
        if (tid == 0) { tv[t] = rv[0]; tix[t] = ri[0]; sim[ri[0]] = -1e30f; }
        __syncthreads();
    }
    if (tid == 0) {
        float mx = tv[0], e[TOPK_], s = 0.f;
#pragma unroll
        for (int t = 0; t < TOPK_; t++) { e[t] = expf(tv[t]-mx); s += e[t]; }
        float inv = 1.f/s;
#pragma unroll
        for (int t = 0; t < TOPK_; t++) { g_w[n*TOPK_+t] = e[t]*inv; g_idx[n*TOPK_+t] = tix[t]; }
    }
}

// ---------------- 3a. score logits ----------------
__global__ void score_kernel(const float* __restrict__ x,
                             const float* __restrict__ Wscore,
                             const float* __restrict__ bscore) {
    int b = blockIdx.y, l0 = blockIdx.x * 90;
    int w = threadIdx.x >> 5, lane = threadIdx.x & 31;
    for (int l = l0 + w; l < l0 + 90; l += 8) {
        const float4* xr = (const float4*)(x + ((size_t)b*L_+l)*N_);
        const float4* wr = (const float4*)Wscore;
        float s = 0.f;
#pragma unroll
        for (int c = 0; c < 4; c++) {
            float4 v = xr[lane + c*32], ww = wr[lane + c*32];
            s += v.x*ww.x + v.y*ww.y + v.z*ww.z + v.w*ww.w;
        }
#pragma unroll
        for (int o = 16; o > 0; o >>= 1) s += __shfl_xor_sync(0xffffffffu, s, o);
        if (lane == 0) g_logit[b*L_+l] = s + bscore[0];
    }
}

// ---------------- 3b. softmax over L ----------------
__global__ void softmax_kernel() {
    int b = blockIdx.x, tid = threadIdx.x;   // 256 threads
    __shared__ float red[256];
    float m = -1e30f;
    for (int l = tid; l < L_; l += 256) m = fmaxf(m, g_logit[b*L_+l]);
    red[tid] = m; __syncthreads();
    for (int o = 128; o > 0; o >>= 1) { if (tid < o) red[tid] = fmaxf(red[tid], red[tid+o]); __syncthreads(); }
    m = red[0]; __syncthreads();
    float s = 0.f;
    for (int l = tid; l < L_; l += 256) s += expf(g_logit[b*L_+l]-m);
    red[tid] = s; __syncthreads();
    for (int o = 128; o > 0; o >>= 1) { if (tid < o) red[tid] += red[tid+o]; __syncthreads(); }
    float inv = 1.f/red[0];
    for (int l = tid; l < L_; l += 256) g_prob[b*L_+l] = expf(g_logit[b*L_+l]-m)*inv;
}

// ---------------- 3c. weighted sum over L ----------------
__global__ void csum_kernel(const float* __restrict__ x) {
    int b = blockIdx.y, c = blockIdx.x*128 + threadIdx.x;
    __shared__ float p[L_];
    for (int l = threadIdx.x; l < L_; l += 128) p[l] = g_prob[b*L_+l];
    __syncthreads();
    float acc = 0.f;
    const float* xb = x + (size_t)b*L_*N_ + c;
    for (int l = 0; l < L_; l++) acc += p[l]*xb[(size_t)l*N_];
    g_center_raw[b*N_+c] = acc;
}

// ---------------- 4a. center MLP ----------------
__global__ void mlp_kernel(const float* __restrict__ Wc1, const float* __restrict__ bc1,
                           const float* __restrict__ Wc2, const float* __restrict__ bc2,
                           const float* __restrict__ Wcn, const float* __restrict__ bcn) {
    int b = blockIdx.x, tid = threadIdx.x;   // 256 threads
    __shared__ float cr[N_];
    __shared__ float c1[D_];
    __shared__ float c2[D_];
    for (int n = tid; n < N_; n += 256) cr[n] = g_center_raw[b*N_+n];
    __syncthreads();
    {
        int d = tid >> 2, part = tid & 3;
        float s = 0.f;
        for (int n = part*128; n < part*128+128; n++) s += cr[n]*Wc1[n*D_+d];
        s += __shfl_xor_sync(0xffffffffu, s, 1);
        s += __shfl_xor_sync(0xffffffffu, s, 2);
        if (part == 0) {
            s += bc1[d];
            c1[d] = 0.5f*s*(1.f + erff(s*0.7071067811865475f));
        }
    }
    __syncthreads();
    if (tid < D_) {
        float s = bc2[tid];
#pragma unroll
        for (int e = 0; e < D_; e++) s += c1[e]*Wc2[e*D_+tid];
        c2[tid] = 0.5f*s*(1.f + erff(s*0.7071067811865475f));
    }
    __syncthreads();
    for (int n = tid; n < N_; n += 256) {
        float s = bcn[n];
#pragma unroll
        for (int d = 0; d < D_; d++) s += c2[d]*Wcn[d*N_+n];
        g_center[b*N_+n] = s;
    }
}

// ---------------- 4b. cg = center @ Wg[N:2N] ----------------
__global__ void cg_kernel(const float* __restrict__ Wg) {
    int b = blockIdx.x, n2 = blockIdx.y*128 + threadIdx.x;
    __shared__ float ctr[N_];
    for (int n = threadIdx.x; n < N_; n += 128) ctr[n] = g_center[b*N_+n];
    __syncthreads();
    float s = 0.f;
    for (int n = 0; n < N_; n++) s += ctr[n]*Wg[(size_t)(N_+n)*N_ + n2];
    g_cg[b*N_+n2] = s;
}

// ---------------- 5. ring gather (fp32, proven R2 version) ----------------
#define TL 8
__global__ void ring_kernel(const float* __restrict__ x) {
    int b = blockIdx.y, l0 = blockIdx.x * TL, tid = threadIdx.x;   // 256 threads
    __shared__ float xt[TL][N_];
    const float* xb = x + (size_t)b*L_*N_ + (size_t)l0*N_;
    for (int i = tid; i < TL*N_/4; i += 256)
        ((float4*)xt)[i] = ((const float4*)xb)[i];
    __syncthreads();
    float* outb = g_ring + (size_t)b*L_*N_ + (size_t)l0*N_;
    for (int o = tid; o < TL*N_; o += 256) {
        int l = o >> 9, n = o & 511;
        float acc = 0.f;
#pragma unroll
        for (int k = 0; k < TOPK_; k++) {
            int id  = __ldg(&g_idx[n*TOPK_+k]);
            float w = __ldg(&g_w[n*TOPK_+k]);
            acc += xt[l][id] * w;
        }
        outb[o] = acc;
    }
}

// ---------------- 6. WMMA bf16-split GEMM, fp32 in / fp32 out, split in-kernel -------
// C = A @ W   (A: M x 512 fp32 row-major; W: 512 x 512 fp32 row-major, used directly)
// mode 0: A=g_ring,  W=Wg(top rows);  epi: sigmoid gate mix -> g_fused (fp32)
// mode 1: A=g_fused, W=Wf;            epi: raw product -> g_h (bias+residual in ln)
#define BM_ 128
#define BN_ 128
#define BK_ 32
#define A_LD 40     // bf16 elems per A smem row
#define W_LD 136    // bf16 elems per W smem row
// byte offsets in dynamic smem
#define SA_H 0
#define SA_L 10240
#define SW_H 20480
#define SW_L 29184
#define GEMM_SMEM_ 37888
#define STG_LD 68   // fp32 staging row stride (mode-0 epilogue, 16 rows per warp pass)

__global__ __launch_bounds__(256) void gemm_wmma(int mode,
                                                 const float* __restrict__ Wmat,
                                                 const float* __restrict__ e0) {
    extern __shared__ __align__(128) char smem[];
    const int tid = threadIdx.x, wid = tid >> 5, lane = tid & 31;
    const int wm = wid >> 1, wn = wid & 1;   // warp grid 4(m) x 2(n): warp tile 32 x 64
    const int row0 = blockIdx.x * BM_, col0 = blockIdx.y * BN_;

    const float* A = (mode == 0) ? g_ring : g_fused;

    __nv_bfloat16* sAh = (__nv_bfloat16*)(smem + SA_H);
    __nv_bfloat16* sAl = (__nv_bfloat16*)(smem + SA_L);
    __nv_bfloat16* sWh = (__nv_bfloat16*)(smem + SW_H);
    __nv_bfloat16* sWl = (__nv_bfloat16*)(smem + SW_L);

    wmma::fragment<wmma::accumulator, 16, 16, 16, float> facc[2][4];
#pragma unroll
    for (int mi = 0; mi < 2; mi++)
#pragma unroll
        for (int p = 0; p < 4; p++) wmma::fill_fragment(facc[mi][p], 0.f);

    const int NKB = N_ / BK_;   // 16
    for (int kb = 0; kb < NKB; kb++) {
        const int k0 = kb * BK_;
        __syncthreads();   // protect smem from previous iteration's readers
        // --- A tile: 128 x 32 fp32 -> split bf16. 1024 float4 chunks.
#pragma unroll
        for (int i = 0; i < 4; i++) {
            int c = i*256 + tid;
            int row = c >> 3, col4 = (c & 7) * 4;
            float4 v = *(const float4*)(A + (size_t)(row0+row)*N_ + k0 + col4);
            __nv_bfloat16 h0,l0_,h1,l1,h2,l2,h3,l3;
            bsplit(v.x, h0, l0_); bsplit(v.y, h1, l1);
            bsplit(v.z, h2, l2);  bsplit(v.w, h3, l3);
            int o = row*A_LD + col4;
            *(__nv_bfloat162*)(sAh + o)     = __nv_bfloat162(h0, h1);
            *(__nv_bfloat162*)(sAh + o + 2) = __nv_bfloat162(h2, h3);
            *(__nv_bfloat162*)(sAl + o)     = __nv_bfloat162(l0_, l1);
            *(__nv_bfloat162*)(sAl + o + 2) = __nv_bfloat162(l2, l3);
        }
        // --- W tile: 32 x 128 fp32 -> split bf16. 1024 float4 chunks.
#pragma unroll
        for (int i = 0; i < 4; i++) {
            int c = i*256 + tid;
            int row = c >> 5, col4 = (c & 31) * 4;
            float4 v = *(const float4*)(Wmat + (size_t)(k0+row)*N_ + col0 + col4);
            __nv_bfloat16 h0,l0_,h1,l1,h2,l2,h3,l3;
            bsplit(v.x, h0, l0_); bsplit(v.y, h1, l1);
            bsplit(v.z, h2, l2);  bsplit(v.w, h3, l3);
            int o = row*W_LD + col4;
            *(__nv_bfloat162*)(sWh + o)     = __nv_bfloat162(h0, h1);
            *(__nv_bfloat162*)(sWh + o + 2) = __nv_bfloat162(h2, h3);
            *(__nv_bfloat162*)(sWl + o)     = __nv_bfloat162(l0_, l1);
            *(__nv_bfloat162*)(sWl + o + 2) = __nv_bfloat162(l2, l3);
        }
        __syncthreads();

#pragma unroll
        for (int ks = 0; ks < 2; ks++) {
            wmma::fragment<wmma::matrix_a, 16, 16, 16, __nv_bfloat16, wmma::row_major> fah[2], fal[2];
#pragma unroll
            for (int mi = 0; mi < 2; mi++) {
                int aro = (wm*32 + mi*16) * A_LD + ks*16;
                wmma::load_matrix_sync(fah[mi], sAh + aro, A_LD);
                wmma::load_matrix_sync(fal[mi], sAl + aro, A_LD);
            }
#pragma unroll
            for (int p = 0; p < 4; p++) {
                wmma::fragment<wmma::matrix_b, 16, 16, 16, __nv_bfloat16, wmma::row_major> fbh, fbl;
                int bro = (ks*16) * W_LD + wn*64 + p*16;
                wmma::load_matrix_sync(fbh, sWh + bro, W_LD);
                wmma::load_matrix_sync(fbl, sWl + bro, W_LD);
#pragma unroll
                for (int mi = 0; mi < 2; mi++) {
                    wmma::mma_sync(facc[mi][p], fah[mi], fbh, facc[mi][p]);
                    wmma::mma_sync(facc[mi][p], fah[mi], fbl, facc[mi][p]);
                    wmma::mma_sync(facc[mi][p], fal[mi], fbh, facc[mi][p]);
                }
            }
        }
    }
    __syncthreads();   // all compute done before smem reuse as staging

    if (mode == 1) {
        // raw product straight to g_h; bias + residual folded into ln_kernel
#pragma unroll
        for (int mi = 0; mi < 2; mi++)
#pragma unroll
            for (int p = 0; p < 4; p++) {
                float* dst = g_h + (size_t)(row0 + wm*32 + mi*16)*N_ + col0 + wn*64 + p*16;
                wmma::store_matrix_sync(dst, facc[mi][p], N_, wmma::mem_row_major);
            }
        return;
    }

    // ---- mode 0 epilogue: two passes of 16 rows via per-warp smem staging ----
    float* wst = (float*)smem + wid * (16 * STG_LD);
#pragma unroll
    for (int mi = 0; mi < 2; mi++) {
#pragma unroll
        for (int p = 0; p < 4; p++)
            wmma::store_matrix_sync(wst + p*16, facc[mi][p], STG_LD, wmma::mem_row_major);
        __syncwarp();
        int r16 = lane >> 1;
        int coff = (lane & 1) * 32;
        int r = row0 + wm*32 + mi*16 + r16;
        int bb = r / L_;
        size_t rb = (size_t)r * N_;
        const float* myrow = wst + r16*STG_LD + coff;
#pragma unroll
        for (int q = 0; q < 8; q++) {
            float4 v = *(const float4*)(myrow + q*4);
            int c = col0 + wn*64 + coff + q*4;
            float4 o;
#pragma unroll
            for (int t = 0; t < 4; t++) {
                int cc = c + t;
                float vv = (&v.x)[t];
                float pre = vv + g_cg[bb*N_+cc] + e0[cc];
                float g = 1.f/(1.f + expf(-pre));
                float rv = g_ring[rb+cc];
                (&o.x)[t] = g*rv + (1.f-g)*g_center[bb*N_+cc];
            }
            *(float4*)(g_fused + rb + c) = o;
        }
        __syncwarp();
    }
}

// ---------------- 7. LayerNorm over N (+ folded Wf bias and residual) ----------------
__global__ void ln_kernel(const float* __restrict__ gamma, const float* __restrict__ beta,
                          const float* __restrict__ bf, const float* __restrict__ x,
                          float* __restrict__ out) {
    int r = blockIdx.x, tid = threadIdx.x;   // 256 threads
    size_t base = (size_t)r*N_;
    float a  = g_h[base+tid]     + bf[tid]     + x[base+tid];
    float b2 = g_h[base+tid+256] + bf[tid+256] + x[base+tid+256];
    __shared__ float rs[256], rq[256];
    rs[tid] = a + b2;
    rq[tid] = a*a + b2*b2;
    __syncthreads();
    for (int o = 128; o > 0; o >>= 1) {
        if (tid < o) { rs[tid] += rs[tid+o]; rq[tid] += rq[tid+o]; }
        __syncthreads();
    }
    float mu  = rs[0] * (1.f/N_);
    float var = rq[0] * (1.f/N_) - mu*mu;
    float inv = rsqrtf(var + 1e-5f);
    out[base+tid]     = (a  - mu)*inv*gamma[tid]     + beta[tid];
    out[base+tid+256] = (b2 - mu)*inv*gamma[tid+256] + beta[tid+256];
}

// ---------------- launch ----------------
extern "C" void kernel_launch(void* const* d_in, const int* in_sizes, int n_in,
                              void* d_out, int out_size) {
    const float* x      = (const float*)d_in[0];
    const float* ve     = (const float*)d_in[1];
    const float* Wq     = (const float*)d_in[2];
    const float* bq     = (const float*)d_in[3];
    const float* Wk     = (const float*)d_in[4];
    const float* bk     = (const float*)d_in[5];
    const float* Wscore = (const float*)d_in[6];
    const float* bscore = (const float*)d_in[7];
    const float* Wc1    = (const float*)d_in[8];
    const float* bc1    = (const float*)d_in[9];
    const float* Wc2    = (const float*)d_in[10];
    const float* bc2    = (const float*)d_in[11];
    const float* Wcn    = (const float*)d_in[12];
    const float* bcn    = (const float*)d_in[13];
    const float* Wg     = (const float*)d_in[14];
    const float* bg     = (const float*)d_in[15];
    const float* Wf     = (const float*)d_in[16];
    const float* bf     = (const float*)d_in[17];
    const float* gamma  = (const float*)d_in[18];
    const float* beta   = (const float*)d_in[19];
    float* out = (float*)d_out;

    cudaFuncSetAttribute(gemm_wmma, cudaFuncAttributeMaxDynamicSharedMemorySize, GEMM_SMEM_);

    qk_kernel<<<2, 256>>>(ve, Wq, bq, Wk, bk);
    topk_kernel<<<512, 128>>>();
    score_kernel<<<dim3(8, B_), 256>>>(x, Wscore, bscore);
    softmax_kernel<<<B_, 256>>>();
    csum_kernel<<<dim3(4, B_), 128>>>(x);
    mlp_kernel<<<B_, 256>>>(Wc1, bc1, Wc2, bc2, Wcn, bcn);
    cg_kernel<<<dim3(B_, 4), 128>>>(Wg);
    ring_kernel<<<dim3(L_/TL, B_), 256>>>(x);

    // gate GEMM (W = Wg top half, used in native row-major layout)
    gemm_wmma<<<dim3(M_/BM_, N_/BN_), 256, GEMM_SMEM_>>>(0, Wg, bg);
    // Wf GEMM, raw product -> g_h (bias+residual in ln)
    gemm_wmma<<<dim3(M_/BM_, N_/BN_), 256, GEMM_SMEM_>>>(1, Wf, nullptr);

    ln_kernel<<<M_, 256>>>(gamma, beta, bf, x, out);
}